// round 17
// baseline (speedup 1.0000x reference)
#include <cuda_runtime.h>
#include <cstdint>

#define T_LEN 2048
#define F_DIM 32
#define B_TOT 512
#define BT    (B_TOT * T_LEN)          // 1,048,576 rows

typedef unsigned long long U;          // packed f32x2 carrier

// ---------------- scratch (__device__ globals) ------------------------------
__device__ float g_gx4[(size_t)BT * 4 * F_DIM];  // [row][f][gate 0..3]  536MB (bias in)
__device__ float g_yx [(size_t)BT * 2 * F_DIM];  // [row][f][half 0..1]  268MB (b_lin in half0)

// ---------------- packed fp32x2 helpers ------------------------------------
__device__ __forceinline__ U ffma2(U a, U b, U c) {
    U d; asm("fma.rn.f32x2 %0, %1, %2, %3;" : "=l"(d) : "l"(a), "l"(b), "l"(c));
    return d;
}
__device__ __forceinline__ U add2(U a, U b) {
    U d; asm("add.rn.f32x2 %0, %1, %2;" : "=l"(d) : "l"(a), "l"(b));
    return d;
}
__device__ __forceinline__ U pack2(float lo, float hi) {
    U d; asm("mov.b64 %0, {%1, %2};" : "=l"(d) : "f"(lo), "f"(hi));
    return d;
}
__device__ __forceinline__ float2 unpk(U d) {
    float2 r; asm("mov.b64 {%0, %1}, %2;" : "=f"(r.x), "=f"(r.y) : "l"(d));
    return r;
}
__device__ __forceinline__ float sum2(U a) {
    float2 s = unpk(a);
    return s.x + s.y;
}
__device__ __forceinline__ float sum4(U a, U b) {
    float2 s = unpk(add2(a, b));
    return s.x + s.y;
}

// ---------------- activations (MUFU.TANH; proven rel_err 4.5e-6) ------------
__device__ __forceinline__ float tanh_f(float x) {
    float y; asm("tanh.approx.f32 %0, %1;" : "=f"(y) : "f"(x));
    return y;
}
__device__ __forceinline__ float sig_f(float x) {
    return fmaf(tanh_f(0.5f * x), 0.5f, 0.5f);
}

// ============================================================================
// K1: per row: gx4[row][f][g] = bias_g + W_ih[g*32+f]·x[row]   (g = 2r, 2r+1)
//     yx[row][f][r] = sum_{j in [16r,16r+16)} W_lin[f][2j+1]·x_j (+b_lin if r=0)
//   (unchanged, proven ~320us)
// ============================================================================
__global__ void __launch_bounds__(128, 4)
k1_xpre(const float* __restrict__ x,
        const float* __restrict__ W_ih,
        const float* __restrict__ b_ih,
        const float* __restrict__ b_hh,
        const float* __restrict__ W_lin,
        const float* __restrict__ b_lin)
{
    __shared__ __align__(16) float xs[2][16][F_DIM];   // 4KB
    const int tid = threadIdx.x;
    const int w = tid >> 5, f = tid & 31;
    const int pairId = w >> 1, r = w & 1;
    const int g0 = 2 * r;
    const U ZERO = pack2(0.0f, 0.0f);

    U wa[16], wb[16], wo[8];
    {
        const U* pa = (const U*)(W_ih + (size_t)(g0 * 32 + f) * 32);
        const U* pb = (const U*)(W_ih + (size_t)((g0 + 1) * 32 + f) * 32);
#pragma unroll
        for (int k = 0; k < 16; k++) { wa[k] = pa[k]; wb[k] = pb[k]; }
        const float* pl = W_lin + (size_t)f * 64;
#pragma unroll
        for (int k = 0; k < 4; k++) {
            wo[2 * k]     = pack2(pl[32 * r + 8 * k + 1], pl[32 * r + 8 * k + 3]);
            wo[2 * k + 1] = pack2(pl[32 * r + 8 * k + 5], pl[32 * r + 8 * k + 7]);
        }
    }
    const float biasA = b_ih[g0 * 32 + f] + b_hh[g0 * 32 + f];
    const float biasB = b_ih[(g0 + 1) * 32 + f] + b_hh[(g0 + 1) * 32 + f];
    const float biasY = r ? 0.0f : b_lin[f];

    const int NT = BT / 16;                    // 65536 tiles
    const int srid = tid >> 3, sseg = tid & 7;

    int tile = blockIdx.x;
    if (tile < NT) {
        *(ulonglong2*)&xs[0][srid][sseg * 4] =
            *(const ulonglong2*)(x + ((size_t)(tile * 16 + srid) * F_DIM + sseg * 4));
    }
    __syncthreads();

    int cur = 0;
    while (tile < NT) {
        const int ntile = tile + gridDim.x;
        const bool have = (ntile < NT);
        ulonglong2 nxt;
        if (have)
            nxt = *(const ulonglong2*)(x +
                  ((size_t)(ntile * 16 + srid) * F_DIM + sseg * 4));

        const int row0 = tile * 16 + pairId * 8;
#pragma unroll
        for (int rr = 0; rr < 8; rr++) {
            const ulonglong2* xz = (const ulonglong2*)&xs[cur][pairId * 8 + rr][0];
            U q0 = pack2(biasA, 0.f), q1 = ZERO;
            U q2 = pack2(biasB, 0.f), q3 = ZERO;
            U y0 = pack2(biasY, 0.f), y1 = ZERO;
#pragma unroll
            for (int i = 0; i < 8; i++) {
                ulonglong2 v = xz[i];
                q0 = ffma2(wa[2 * i],     v.x, q0);
                q1 = ffma2(wa[2 * i + 1], v.y, q1);
                q2 = ffma2(wb[2 * i],     v.x, q2);
                q3 = ffma2(wb[2 * i + 1], v.y, q3);
            }
#pragma unroll
            for (int k = 0; k < 4; k++) {
                ulonglong2 v = xz[4 * r + k];
                y0 = ffma2(wo[2 * k],     v.x, y0);
                y1 = ffma2(wo[2 * k + 1], v.y, y1);
            }
            const size_t row = (size_t)(row0 + rr);
            *(float2*)&g_gx4[row * 128 + f * 4 + g0] =
                make_float2(sum4(q0, q1), sum4(q2, q3));
            g_yx[row * 64 + f * 2 + r] = sum4(y0, y1);
        }
        if (have)
            *(ulonglong2*)&xs[cur ^ 1][srid][sseg * 4] = nxt;
        __syncthreads();
        cur ^= 1;
        tile = ntile;
    }
}

// ============================================================================
// K2: recurrence, 2 INDEPENDENT BATCHES PER WARP (ILP fills the chain stalls).
//   Weights shared across the pair. Zero barriers; h round-trips through
//   private smem rows. 256 warps (block 64, grid 128) -> warp ~owns an SMSP.
// ============================================================================
__global__ void __launch_bounds__(64, 1)
k2_recur(const float* __restrict__ W_hh,
         const float* __restrict__ W_lin,
         float* __restrict__ out)
{
    __shared__ __align__(16) float hs[2][2][F_DIM];   // [warp][batch][f]

    const int w = threadIdx.x >> 5;     // warp in CTA (0/1)
    const int l = threadIdx.x & 31;     // lane = feature
    const int bA = (blockIdx.x * 2 + w) * 2;      // first of the 2 batches
    const int bB = bA + 1;
    const U ZERO = pack2(0.0f, 0.0f);

    // shared weights: W_hh rows for all 4 gates at feature l
    U whh[4][16];
#pragma unroll
    for (int g = 0; g < 4; g++) {
        const U* p = (const U*)(W_hh + (size_t)(g * 32 + l) * 32);
#pragma unroll
        for (int k = 0; k < 16; k++) whh[g][k] = p[k];
    }
    // out-linear even weights: pair m = (W[l][4m], W[l][4m+2])
    U wlh[16];
    {
        const float* pl = W_lin + (size_t)l * 64;
#pragma unroll
        for (int m = 0; m < 16; m++) wlh[m] = pack2(pl[4 * m], pl[4 * m + 2]);
    }

    const float4* gxpA = (const float4*)(g_gx4 + (size_t)bA * T_LEN * 128) + l;
    const float4* gxpB = (const float4*)(g_gx4 + (size_t)bB * T_LEN * 128) + l;
    const float2* yxpA = (const float2*)(g_yx  + (size_t)bA * T_LEN * 64)  + l;
    const float2* yxpB = (const float2*)(g_yx  + (size_t)bB * T_LEN * 64)  + l;
    float* opA = out + (size_t)bA * T_LEN * F_DIM + l;
    float* opB = out + (size_t)bB * T_LEN * F_DIM + l;

    float cA = 0.0f, cB = 0.0f;
    float4 gxrA[2], gxrB[2];     // slot t&1 = row t
    float2 yxrA[2], yxrB[2];     // slot (t-1)&1 = row t-1
    gxrA[0] = gxpA[0]; gxrA[1] = gxpA[32];
    gxrB[0] = gxpB[0]; gxrB[1] = gxpB[32];
    yxrA[0] = yxpA[0]; yxrA[1] = yxpA[0];   // slot1 junk (unused at t=0)
    yxrB[0] = yxpB[0]; yxrB[1] = yxpB[0];

    hs[w][0][l] = 0.0f;
    hs[w][1][l] = 0.0f;
    __syncwarp();

    for (int tb = 0; tb < T_LEN; tb += 2) {
#pragma unroll
        for (int u = 0; u < 2; u++) {
            const int t = tb + u;

            // ---- dual gate-dots + out-even over h_{t-1} ----
            const ulonglong2* hA = (const ulonglong2*)&hs[w][0][0];
            const ulonglong2* hB = (const ulonglong2*)&hs[w][1][0];
            float4 gA = gxrA[u], gB = gxrB[u];
            U aiA = pack2(gA.x, 0.f), afA = pack2(gA.y, 0.f);
            U agA = pack2(gA.z, 0.f), aoA = pack2(gA.w, 0.f), olA = ZERO;
            U aiB = pack2(gB.x, 0.f), afB = pack2(gB.y, 0.f);
            U agB = pack2(gB.z, 0.f), aoB = pack2(gB.w, 0.f), olB = ZERO;
#pragma unroll
            for (int i = 0; i < 8; i++) {
                ulonglong2 vA = hA[i];
                ulonglong2 vB = hB[i];
                aiA = ffma2(whh[0][2 * i],     vA.x, aiA);
                aiB = ffma2(whh[0][2 * i],     vB.x, aiB);
                afA = ffma2(whh[1][2 * i],     vA.x, afA);
                afB = ffma2(whh[1][2 * i],     vB.x, afB);
                agA = ffma2(whh[2][2 * i],     vA.x, agA);
                agB = ffma2(whh[2][2 * i],     vB.x, agB);
                aoA = ffma2(whh[3][2 * i],     vA.x, aoA);
                aoB = ffma2(whh[3][2 * i],     vB.x, aoB);
                olA = ffma2(wlh[2 * i],        vA.x, olA);
                olB = ffma2(wlh[2 * i],        vB.x, olB);
                aiA = ffma2(whh[0][2 * i + 1], vA.y, aiA);
                aiB = ffma2(whh[0][2 * i + 1], vB.y, aiB);
                afA = ffma2(whh[1][2 * i + 1], vA.y, afA);
                afB = ffma2(whh[1][2 * i + 1], vB.y, afB);
                agA = ffma2(whh[2][2 * i + 1], vA.y, agA);
                agB = ffma2(whh[2][2 * i + 1], vB.y, agB);
                aoA = ffma2(whh[3][2 * i + 1], vA.y, aoA);
                aoB = ffma2(whh[3][2 * i + 1], vB.y, aoB);
                olA = ffma2(wlh[2 * i + 1],    vA.y, olA);
                olB = ffma2(wlh[2 * i + 1],    vB.y, olB);
            }
            float giA = sig_f (sum2(aiA)), giB = sig_f (sum2(aiB));
            float gfA = sig_f (sum2(afA)), gfB = sig_f (sum2(afB));
            float ggA = tanh_f(sum2(agA)), ggB = tanh_f(sum2(agB));
            float goA = sig_f (sum2(aoA)), goB = sig_f (sum2(aoB));
            float ohsA = sum2(olA), ohsB = sum2(olB);

            // ---- ring refills (2-step cover) ----
            {
                int pt = t + 2; if (pt > T_LEN - 1) pt = T_LEN - 1;
                gxrA[u] = gxpA[(size_t)pt * 32];
                gxrB[u] = gxpB[(size_t)pt * 32];
            }
            float2 yvA = yxrA[(t - 1) & 1];
            float2 yvB = yxrB[(t - 1) & 1];
            {
                int pt = t + 1; if (pt > T_LEN - 1) pt = T_LEN - 1;
                yxrA[(t - 1) & 1] = yxpA[(size_t)pt * 32];
                yxrB[(t - 1) & 1] = yxpB[(size_t)pt * 32];
            }

            // ---- finish out_{t-1} ----
            if (t > 0) {
                opA[(size_t)(t - 1) * F_DIM] = tanh_f(ohsA + yvA.x + yvA.y);
                opB[(size_t)(t - 1) * F_DIM] = tanh_f(ohsB + yvB.x + yvB.y);
            }

            // ---- lane-local state updates ----
            cA = gfA * cA + giA * ggA;
            cB = gfB * cB + giB * ggB;
            float hA_ = goA * tanh_f(cA);
            float hB_ = goB * tanh_f(cB);
            hs[w][0][l] = hA_;
            hs[w][1][l] = hB_;
            __syncwarp();
        }
    }

    // ---- epilogue: out_{T-1}; yx[T-1] sits in slot (T-2)&1 = 0 ----
    {
        const ulonglong2* hA = (const ulonglong2*)&hs[w][0][0];
        const ulonglong2* hB = (const ulonglong2*)&hs[w][1][0];
        U olA = ZERO, olB = ZERO;
#pragma unroll
        for (int i = 0; i < 8; i++) {
            ulonglong2 vA = hA[i];
            ulonglong2 vB = hB[i];
            olA = ffma2(wlh[2 * i],     vA.x, olA);
            olB = ffma2(wlh[2 * i],     vB.x, olB);
            olA = ffma2(wlh[2 * i + 1], vA.y, olA);
            olB = ffma2(wlh[2 * i + 1], vB.y, olB);
        }
        float2 yvA = yxrA[(T_LEN - 2) & 1];
        float2 yvB = yxrB[(T_LEN - 2) & 1];
        opA[(size_t)(T_LEN - 1) * F_DIM] = tanh_f(sum2(olA) + yvA.x + yvA.y);
        opB[(size_t)(T_LEN - 1) * F_DIM] = tanh_f(sum2(olB) + yvB.x + yvB.y);
    }
}

// ============================================================================
extern "C" void kernel_launch(void* const* d_in, const int* in_sizes, int n_in,
                              void* d_out, int out_size)
{
    const float* x     = (const float*)d_in[0];
    const float* W_ih  = (const float*)d_in[1];
    const float* W_hh  = (const float*)d_in[2];
    const float* b_ih  = (const float*)d_in[3];
    const float* b_hh  = (const float*)d_in[4];
    const float* W_lin = (const float*)d_in[5];
    const float* b_lin = (const float*)d_in[6];
    float* out = (float*)d_out;

    k1_xpre<<<592, 128>>>(x, W_ih, b_ih, b_hh, W_lin, b_lin);   // all 148 SMs
    k2_recur<<<128, 64>>>(W_hh, W_lin, out);   // 256 warps, 2 batches each
}